// round 7
// baseline (speedup 1.0000x reference)
#include <cuda_runtime.h>
#include <math.h>

#define P_MAX  32768
#define NCELLS 4096
#define SORT_BLOCKS  148
#define SORT_THREADS 256

// ---------------- device scratch (no allocation allowed) --------------------
__device__ int    g_counts[NCELLS];
__device__ int    g_cursor[NCELLS];
__device__ int    g_start[NCELLS];
__device__ int    g_cell[P_MAX];
__device__ float4 g_pt[P_MAX];    // sorted (x0,x1,x2, bitcast(orig p))
__device__ float4 g_dir[P_MAX];   // sorted (d0,d1,d2, 0)
__device__ unsigned          g_bar_cnt;
__device__ volatile unsigned g_bar_gen;

// ---------------- helpers ---------------------------------------------------
__device__ __forceinline__ int cell_of(float x0, float x1, float x2) {
    float v0 = x0 / 0.1875f + 8.0f;
    float v1 = x1 / 0.1875f + 8.0f;
    float v2 = x2 / 0.1875f + 8.0f;
    int i0 = (int)v0; i0 = min(max(i0, 0), 15);
    int i1 = (int)v1; i1 = min(max(i1, 0), 15);
    int i2 = (int)v2; i2 = min(max(i2, 0), 15);
    return (i0 * 16 + i1) * 16 + i2;
}

__device__ __forceinline__ void gridbar() {
    __syncthreads();
    if (threadIdx.x == 0) {
        unsigned gen = g_bar_gen;
        __threadfence();
        unsigned arrived = atomicAdd(&g_bar_cnt, 1u);
        if (arrived == gridDim.x - 1) {
            g_bar_cnt = 0;
            __threadfence();
            g_bar_gen = gen + 1;
        } else {
            while (g_bar_gen == gen) { __nanosleep(64); }
            __threadfence();
        }
    }
    __syncthreads();
}

// ---------------- kernel 1: counting sort (persistent) ----------------------
__global__ __launch_bounds__(SORT_THREADS) void k_sort(
    const float* __restrict__ x, const float* __restrict__ d, int P)
{
    int tid  = blockIdx.x * blockDim.x + threadIdx.x;
    int nthr = gridDim.x * blockDim.x;

    for (int c = tid; c < NCELLS; c += nthr) g_counts[c] = 0;
    gridbar();

    for (int p = tid; p < P; p += nthr) {
        int c = cell_of(x[3 * p], x[3 * p + 1], x[3 * p + 2]);
        g_cell[p] = c;
        atomicAdd(&g_counts[c], 1);
    }
    gridbar();

    if (blockIdx.x == 0) {            // exclusive scan: 256 thr x 16 cells
        __shared__ int s[SORT_THREADS];
        int t = threadIdx.x;
        int cnt[16]; int sum = 0;
        #pragma unroll
        for (int j = 0; j < 16; j++) { cnt[j] = g_counts[t * 16 + j]; sum += cnt[j]; }
        s[t] = sum;
        __syncthreads();
        #pragma unroll
        for (int off = 1; off < SORT_THREADS; off <<= 1) {
            int u = (t >= off) ? s[t - off] : 0;
            __syncthreads();
            s[t] += u;
            __syncthreads();
        }
        int run = s[t] - sum;
        #pragma unroll
        for (int j = 0; j < 16; j++) {
            g_start[t * 16 + j]  = run;
            g_cursor[t * 16 + j] = run;
            run += cnt[j];
        }
    }
    gridbar();

    for (int p = tid; p < P; p += nthr) {
        int c = g_cell[p];
        int pos = atomicAdd(&g_cursor[c], 1);
        g_pt[pos]  = make_float4(x[3 * p], x[3 * p + 1], x[3 * p + 2], __int_as_float(p));
        g_dir[pos] = make_float4(d[3 * p], d[3 * p + 1], d[3 * p + 2], 0.0f);
    }
}

// -------- MLP micro-op: 4 outputs, one float4 SMEM read ---------------------
__device__ __forceinline__ void fma4s(float hv, const float4* __restrict__ w4,
                                      float* __restrict__ acc) {
    float4 a = *w4;
    acc[0] = fmaf(hv, a.x, acc[0]); acc[1] = fmaf(hv, a.y, acc[1]);
    acc[2] = fmaf(hv, a.z, acc[2]); acc[3] = fmaf(hv, a.w, acc[3]);
}

// -------- kernel 2: one block per cell; weights staged in SMEM --------------
__global__ __launch_bounds__(64) void k_mlp(
    const float* __restrict__ l1w, const float* __restrict__ l1b,
    const float* __restrict__ l2w, const float* __restrict__ l2b,
    const float* __restrict__ l3w, const float* __restrict__ l3b,
    const float* __restrict__ l4w, const float* __restrict__ l4b,
    const float* __restrict__ l5w, const float* __restrict__ l5b,
    float* __restrict__ out, int P)
{
    __shared__ __align__(16) float s_w1[2016];
    __shared__ __align__(16) float s_b1[32];
    __shared__ __align__(16) float s_w2[1024];
    __shared__ __align__(16) float s_w2d[32];
    __shared__ __align__(16) float s_b2[32];
    __shared__ __align__(16) float s_w3[1024];
    __shared__ __align__(16) float s_b3[32];
    __shared__ __align__(16) float s_w4[1888];
    __shared__ __align__(16) float s_b4[32];
    __shared__ __align__(16) float s_w5[96];
    __shared__ float s_b5[3];
    __shared__ float s_bd2;

    int cell = blockIdx.x;
    int cnt  = g_counts[cell];
    if (cnt == 0) return;            // uniform exit, before any __syncthreads
    int cstart = g_start[cell];
    int tid = threadIdx.x;

    // ---- cooperative weight staging (coalesced float4 streams) ----
    {
        const float4* s = (const float4*)(l1w + (size_t)cell * 2016);
        float4* dd = (float4*)s_w1;
        for (int i = tid; i < 504; i += 64) dd[i] = __ldg(s + i);
    }
    {
        const float4* s = (const float4*)(l3w + (size_t)cell * 1024);
        float4* dd = (float4*)s_w3;
        for (int i = tid; i < 256; i += 64) dd[i] = __ldg(s + i);
    }
    {
        const float4* s = (const float4*)(l4w + (size_t)cell * 1888);
        float4* dd = (float4*)s_w4;
        for (int i = tid; i < 472; i += 64) dd[i] = __ldg(s + i);
    }
    {   // layer-2: repack stride 33 -> stride 32 + density column (free here)
        const float* s = l2w + (size_t)cell * 1056;
        for (int e = tid; e < 1056; e += 64) {
            float v = __ldg(s + e);
            int i = e / 33, o = e - i * 33;
            if (o < 32) s_w2[i * 32 + o] = v;
            else        s_w2d[i] = v;
        }
    }
    {
        const float4* s = (const float4*)(l5w + (size_t)cell * 96);
        float4* dd = (float4*)s_w5;
        if (tid < 24) dd[tid] = __ldg(s + tid);
    }
    if (tid < 8) {
        ((float4*)s_b1)[tid] = __ldg((const float4*)(l1b + cell * 32) + tid);
        ((float4*)s_b3)[tid] = __ldg((const float4*)(l3b + cell * 32) + tid);
        ((float4*)s_b4)[tid] = __ldg((const float4*)(l4b + cell * 32) + tid);
    }
    if (tid < 33) {
        float v = __ldg(l2b + cell * 33 + tid);
        if (tid < 32) s_b2[tid] = v;
        else          s_bd2 = v;
    }
    if (tid >= 40 && tid < 43) s_b5[tid - 40] = __ldg(l5b + cell * 3 + (tid - 40));
    __syncthreads();

    // ---- compute: waves of 8 points, 8 lanes/point, 4 outputs/lane ----
    int sub = tid & 7;
    unsigned lanebase = ((unsigned)tid & 31u) & ~7u;
    unsigned gm = 0xFFu << lanebase;

    for (int base = 0; base < cnt; base += 8) {
        int slot = base + (tid >> 3);
        if (slot >= cnt) break;          // group-uniform; no sync below

        float4 xv = g_pt[cstart + slot];
        float4 dv = g_dir[cstart + slot];
        int p = __float_as_int(xv.w);
        bool mask = (fabsf(xv.x) < 1.5f) && (fabsf(xv.y) < 1.5f) && (fabsf(xv.z) < 1.5f);

        float acc[4], prev[4];

        // ==== layer 1: 63 -> 32, relu (inputs by recurrence) ====
        {
            const float4* b4 = (const float4*)s_b1 + sub;
            float4 b0 = *b4;
            acc[0] = b0.x; acc[1] = b0.y; acc[2] = b0.z; acc[3] = b0.w;
            const float4* w1 = (const float4*)s_w1 + sub;
            fma4s(xv.x, w1 + 0 * 8, acc);
            fma4s(xv.y, w1 + 1 * 8, acc);
            fma4s(xv.z, w1 + 2 * 8, acc);
            float s0 = sinf(xv.x), c0 = cosf(xv.x);
            float s1 = sinf(xv.y), c1 = cosf(xv.y);
            float s2 = sinf(xv.z), c2 = cosf(xv.z);
            #pragma unroll 1
            for (int j = 0; j < 10; j++) {
                const float4* wr = w1 + (3 + 6 * j) * 8;
                fma4s(s0, wr + 0 * 8, acc);
                fma4s(s1, wr + 1 * 8, acc);
                fma4s(s2, wr + 2 * 8, acc);
                fma4s(c0, wr + 3 * 8, acc);
                fma4s(c1, wr + 4 * 8, acc);
                fma4s(c2, wr + 5 * 8, acc);
                float n0 = 2.0f * s0 * c0, m0 = 1.0f - 2.0f * s0 * s0;
                float n1 = 2.0f * s1 * c1, m1 = 1.0f - 2.0f * s1 * s1;
                float n2 = 2.0f * s2 * c2, m2 = 1.0f - 2.0f * s2 * s2;
                s0 = n0; c0 = m0; s1 = n1; c1 = m1; s2 = n2; c2 = m2;
            }
            #pragma unroll
            for (int q = 0; q < 4; q++) prev[q] = fmaxf(acc[q], 0.0f);
        }

        // ==== layer 2 (repacked in smem): 32 -> 32 + density column ====
        float dens = 0.0f;
        {
            const float4* b4 = (const float4*)s_b2 + sub;
            float4 b0 = *b4;
            acc[0] = b0.x; acc[1] = b0.y; acc[2] = b0.z; acc[3] = b0.w;
            if (sub == 7) dens = s_bd2;
            const float4* w2 = (const float4*)s_w2 + sub;
            #pragma unroll 4
            for (int g = 0; g < 8; g++) {
                int src = lanebase + g;
                #pragma unroll
                for (int j = 0; j < 4; j++) {
                    float hv = __shfl_sync(gm, prev[j], src);
                    fma4s(hv, w2 + (g * 4 + j) * 8, acc);
                    if (sub == 7) dens = fmaf(hv, s_w2d[g * 4 + j], dens);
                }
            }
            dens = fmaxf(dens, 0.0f);
            #pragma unroll
            for (int q = 0; q < 4; q++) prev[q] = fmaxf(acc[q], 0.0f);
        }

        // ==== layer 3: 32 -> 32, NO activation ====
        {
            const float4* b4 = (const float4*)s_b3 + sub;
            float4 b0 = *b4;
            acc[0] = b0.x; acc[1] = b0.y; acc[2] = b0.z; acc[3] = b0.w;
            const float4* w3 = (const float4*)s_w3 + sub;
            #pragma unroll 4
            for (int g = 0; g < 8; g++) {
                int src = lanebase + g;
                #pragma unroll
                for (int j = 0; j < 4; j++) {
                    float hv = __shfl_sync(gm, prev[j], src);
                    fma4s(hv, w3 + (g * 4 + j) * 8, acc);
                }
            }
            #pragma unroll
            for (int q = 0; q < 4; q++) prev[q] = acc[q];
        }

        // ==== layer 4: 59 -> 32, relu (32 via shfl + 27 dir recurrence) ====
        {
            const float4* b4 = (const float4*)s_b4 + sub;
            float4 b0 = *b4;
            acc[0] = b0.x; acc[1] = b0.y; acc[2] = b0.z; acc[3] = b0.w;
            const float4* w4 = (const float4*)s_w4 + sub;
            #pragma unroll 4
            for (int g = 0; g < 8; g++) {
                int src = lanebase + g;
                #pragma unroll
                for (int j = 0; j < 4; j++) {
                    float hv = __shfl_sync(gm, prev[j], src);
                    fma4s(hv, w4 + (g * 4 + j) * 8, acc);
                }
            }
            fma4s(dv.x, w4 + 32 * 8, acc);
            fma4s(dv.y, w4 + 33 * 8, acc);
            fma4s(dv.z, w4 + 34 * 8, acc);
            float s0 = sinf(dv.x), c0 = cosf(dv.x);
            float s1 = sinf(dv.y), c1 = cosf(dv.y);
            float s2 = sinf(dv.z), c2 = cosf(dv.z);
            #pragma unroll 1
            for (int j = 0; j < 4; j++) {
                const float4* wr = w4 + (35 + 6 * j) * 8;
                fma4s(s0, wr + 0 * 8, acc);
                fma4s(s1, wr + 1 * 8, acc);
                fma4s(s2, wr + 2 * 8, acc);
                fma4s(c0, wr + 3 * 8, acc);
                fma4s(c1, wr + 4 * 8, acc);
                fma4s(c2, wr + 5 * 8, acc);
                float n0 = 2.0f * s0 * c0, m0 = 1.0f - 2.0f * s0 * s0;
                float n1 = 2.0f * s1 * c1, m1 = 1.0f - 2.0f * s1 * s1;
                float n2 = 2.0f * s2 * c2, m2 = 1.0f - 2.0f * s2 * s2;
                s0 = n0; c0 = m0; s1 = n1; c1 = m1; s2 = n2; c2 = m2;
            }
            #pragma unroll
            for (int q = 0; q < 4; q++) prev[q] = fmaxf(acc[q], 0.0f);
        }

        // ==== layer 5: 32 -> 3, sigmoid ====
        {
            int o = min(sub, 2);
            float a5 = s_b5[o];
            #pragma unroll 4
            for (int g = 0; g < 8; g++) {
                int src = lanebase + g;
                #pragma unroll
                for (int j = 0; j < 4; j++) {
                    float hv = __shfl_sync(gm, prev[j], src);
                    a5 = fmaf(hv, s_w5[(g * 4 + j) * 3 + o], a5);
                }
            }
            float cv = 1.0f / (1.0f + expf(-a5));
            if (sub < 3)       out[3 * p + sub] = mask ? cv : 0.0f;
            else if (sub == 7) out[3 * P + p]   = mask ? dens : 0.0f;
        }
    }
}

// ---------------- launch ----------------------------------------------------
extern "C" void kernel_launch(void* const* d_in, const int* in_sizes, int n_in,
                              void* d_out, int out_size) {
    const float* x   = (const float*)d_in[0];
    const float* d   = (const float*)d_in[1];
    const float* l1w = (const float*)d_in[2];
    const float* l1b = (const float*)d_in[3];
    const float* l2w = (const float*)d_in[4];
    const float* l2b = (const float*)d_in[5];
    const float* l3w = (const float*)d_in[6];
    const float* l3b = (const float*)d_in[7];
    const float* l4w = (const float*)d_in[8];
    const float* l4b = (const float*)d_in[9];
    const float* l5w = (const float*)d_in[10];
    const float* l5b = (const float*)d_in[11];
    float* out = (float*)d_out;

    int P = in_sizes[0] / 3;
    if (P > P_MAX) P = P_MAX;

    k_sort<<<SORT_BLOCKS, SORT_THREADS>>>(x, d, P);
    k_mlp<<<NCELLS, 64>>>(l1w, l1b, l2w, l2b, l3w, l3b,
                          l4w, l4b, l5w, l5b, out, P);
}

// round 8
// speedup vs baseline: 1.6501x; 1.6501x over previous
#include <cuda_runtime.h>
#include <math.h>

#define P_MAX  32768
#define NCELLS 4096
#define SORT_BLOCKS  148
#define SORT_THREADS 256

// ---------------- device scratch (no allocation allowed) --------------------
__device__ int    g_counts[NCELLS];
__device__ int    g_cursor[NCELLS];
__device__ int    g_cell[P_MAX];
__device__ float4 g_pt[P_MAX];    // sorted (x0,x1,x2, bitcast(orig p))
__device__ float4 g_dir[P_MAX];   // sorted (d0,d1,d2, 0)
__device__ unsigned          g_bar_cnt;
__device__ volatile unsigned g_bar_gen;

// ---------------- helpers ---------------------------------------------------
__device__ __forceinline__ int cell_of(float x0, float x1, float x2) {
    float v0 = x0 / 0.1875f + 8.0f;
    float v1 = x1 / 0.1875f + 8.0f;
    float v2 = x2 / 0.1875f + 8.0f;
    int i0 = (int)v0; i0 = min(max(i0, 0), 15);
    int i1 = (int)v1; i1 = min(max(i1, 0), 15);
    int i2 = (int)v2; i2 = min(max(i2, 0), 15);
    return (i0 * 16 + i1) * 16 + i2;
}

__device__ __forceinline__ void gridbar() {
    __syncthreads();
    if (threadIdx.x == 0) {
        unsigned gen = g_bar_gen;
        __threadfence();
        unsigned arrived = atomicAdd(&g_bar_cnt, 1u);
        if (arrived == gridDim.x - 1) {
            g_bar_cnt = 0;
            __threadfence();
            g_bar_gen = gen + 1;
        } else {
            while (g_bar_gen == gen) { __nanosleep(64); }
            __threadfence();
        }
    }
    __syncthreads();
}

// ---------------- kernel 1: counting sort (persistent) ----------------------
__global__ __launch_bounds__(SORT_THREADS) void k_sort(
    const float* __restrict__ x, const float* __restrict__ d, int P)
{
    int tid  = blockIdx.x * blockDim.x + threadIdx.x;
    int nthr = gridDim.x * blockDim.x;

    for (int c = tid; c < NCELLS; c += nthr) g_counts[c] = 0;
    gridbar();

    for (int p = tid; p < P; p += nthr) {
        int c = cell_of(x[3 * p], x[3 * p + 1], x[3 * p + 2]);
        g_cell[p] = c;
        atomicAdd(&g_counts[c], 1);
    }
    gridbar();

    if (blockIdx.x == 0) {            // exclusive scan: 256 thr x 16 cells
        __shared__ int s[SORT_THREADS];
        int t = threadIdx.x;
        int cnt[16]; int sum = 0;
        #pragma unroll
        for (int j = 0; j < 16; j++) { cnt[j] = g_counts[t * 16 + j]; sum += cnt[j]; }
        s[t] = sum;
        __syncthreads();
        #pragma unroll
        for (int off = 1; off < SORT_THREADS; off <<= 1) {
            int u = (t >= off) ? s[t - off] : 0;
            __syncthreads();
            s[t] += u;
            __syncthreads();
        }
        int run = s[t] - sum;
        #pragma unroll
        for (int j = 0; j < 16; j++) { g_cursor[t * 16 + j] = run; run += cnt[j]; }
    }
    gridbar();

    for (int p = tid; p < P; p += nthr) {
        int c = g_cell[p];
        int pos = atomicAdd(&g_cursor[c], 1);
        g_pt[pos]  = make_float4(x[3 * p], x[3 * p + 1], x[3 * p + 2], __int_as_float(p));
        g_dir[pos] = make_float4(d[3 * p], d[3 * p + 1], d[3 * p + 2], 0.0f);
    }
}

// ---------------- MLP micro-op: 4 outputs, one float4 load ------------------
__device__ __forceinline__ void fma4(float hv, const float4* __restrict__ w4,
                                     float* __restrict__ acc) {
    float4 a = __ldg(w4);
    acc[0] = fmaf(hv, a.x, acc[0]); acc[1] = fmaf(hv, a.y, acc[1]);
    acc[2] = fmaf(hv, a.z, acc[2]); acc[3] = fmaf(hv, a.w, acc[3]);
}

// cooperative encoding: 8 lanes of a point fill s_emb[slot][0..3+6*L-1+3]
// layout: [0..2]=v, [3+6j+q]=sin(2^j v_q), [6+6j+q]=cos(2^j v_q)
template <int L>
__device__ __forceinline__ void coop_encode(float* __restrict__ dstbase,
                                            float v0, float v1, float v2,
                                            int sub, unsigned gm) {
    if (sub < 6) {
        int q = (sub < 3) ? sub : sub - 3;
        float vq = (q == 0) ? v0 : (q == 1) ? v1 : v2;
        float s = sinf(vq), cc = cosf(vq);
        bool sel = (sub < 3);
        float* dst = dstbase + (sel ? 3 : 6) + q;
        #pragma unroll
        for (int j = 0; j < L; j++) {
            dst[6 * j] = sel ? s : cc;
            float ns = 2.0f * s * cc;
            float nc = 1.0f - 2.0f * s * s;
            s = ns; cc = nc;
        }
    } else if (sub == 6) {
        dstbase[0] = v0; dstbase[1] = v1; dstbase[2] = v2;
    }
    __syncwarp(gm);
}

// ---------------- kernel 2: MLP (8 threads / point, 4 outputs each) ---------
__global__ __launch_bounds__(256, 4) void k_mlp(
    const float* __restrict__ l1w, const float* __restrict__ l1b,
    const float* __restrict__ l2w, const float* __restrict__ l2b,
    const float* __restrict__ l3w, const float* __restrict__ l3b,
    const float* __restrict__ l4w, const float* __restrict__ l4b,
    const float* __restrict__ l5w, const float* __restrict__ l5b,
    float* __restrict__ out, int P)
{
    __shared__ __align__(16) float s_emb[32][68];   // 68 stride: 16B-aligned, conflict-free

    int t   = blockIdx.x * 256 + threadIdx.x;
    int pi  = t >> 3;
    int sub = t & 7;
    if (pi >= P) return;
    int slot = threadIdx.x >> 3;

    float4 xv = g_pt[pi];
    float4 dv = g_dir[pi];
    int p = __float_as_int(xv.w);
    int c = cell_of(xv.x, xv.y, xv.z);
    bool mask = (fabsf(xv.x) < 1.5f) && (fabsf(xv.y) < 1.5f) && (fabsf(xv.z) < 1.5f);
    int lanebase = (threadIdx.x & 31) & ~7;   // lane of sub==0 for this point
    unsigned gm = 0xFFu << lanebase;

    float acc[4], prev[4];
    const float* em = s_emb[slot];

    // ---- cooperative positional encoding (63 entries) into smem ----
    coop_encode<10>(s_emb[slot], xv.x, xv.y, xv.z, sub, gm);

    // ======== layer 1: 63 -> 32, relu — pure stream, deep batching ==========
    {
        const float4* b4 = (const float4*)(l1b + c * 32) + sub;
        float4 b0 = __ldg(b4);
        acc[0] = b0.x; acc[1] = b0.y; acc[2] = b0.z; acc[3] = b0.w;
        const float4* w1 = (const float4*)(l1w + (size_t)c * 2016) + sub;
        #pragma unroll
        for (int i4 = 0; i4 < 15; i4++) {
            float4 e = *(const float4*)(em + 4 * i4);
            fma4(e.x, w1 + (4 * i4 + 0) * 8, acc);
            fma4(e.y, w1 + (4 * i4 + 1) * 8, acc);
            fma4(e.z, w1 + (4 * i4 + 2) * 8, acc);
            fma4(e.w, w1 + (4 * i4 + 3) * 8, acc);
        }
        fma4(em[60], w1 + 60 * 8, acc);
        fma4(em[61], w1 + 61 * 8, acc);
        fma4(em[62], w1 + 62 * 8, acc);
        #pragma unroll
        for (int q = 0; q < 4; q++) prev[q] = fmaxf(acc[q], 0.0f);
    }

    // ======== layer 2: 32 -> 33 (stride 33, scalar), relu; col32 = density ==
    float dens = 0.0f;
    {
        int o0 = sub * 4;
        const float* base = l2w + (size_t)c * 1056 + o0;
        #pragma unroll
        for (int q = 0; q < 4; q++) acc[q] = __ldg(l2b + c * 33 + o0 + q);
        if (sub == 7) dens = __ldg(l2b + c * 33 + 32);
        #pragma unroll 4
        for (int g = 0; g < 8; g++) {
            int src = lanebase + g;
            #pragma unroll
            for (int j = 0; j < 4; j++) {
                float hv = __shfl_sync(gm, prev[j], src);
                const float* wr = base + (g * 4 + j) * 33;
                acc[0] = fmaf(hv, __ldg(wr + 0), acc[0]);
                acc[1] = fmaf(hv, __ldg(wr + 1), acc[1]);
                acc[2] = fmaf(hv, __ldg(wr + 2), acc[2]);
                acc[3] = fmaf(hv, __ldg(wr + 3), acc[3]);
                if (sub == 7) dens = fmaf(hv, __ldg(wr + 4), dens);  // o0=28 -> col 32
            }
        }
        dens = fmaxf(dens, 0.0f);
        #pragma unroll
        for (int q = 0; q < 4; q++) prev[q] = fmaxf(acc[q], 0.0f);
    }

    // ======== layer 3: 32 -> 32, NO activation ==============================
    {
        const float4* b4 = (const float4*)(l3b + c * 32) + sub;
        float4 b0 = __ldg(b4);
        acc[0] = b0.x; acc[1] = b0.y; acc[2] = b0.z; acc[3] = b0.w;
        const float4* w3 = (const float4*)(l3w + (size_t)c * 1024) + sub;
        #pragma unroll 4
        for (int g = 0; g < 8; g++) {
            int src = lanebase + g;
            #pragma unroll
            for (int j = 0; j < 4; j++) {
                float hv = __shfl_sync(gm, prev[j], src);
                fma4(hv, w3 + (g * 4 + j) * 8, acc);
            }
        }
        #pragma unroll
        for (int q = 0; q < 4; q++) prev[q] = acc[q];
    }

    // ---- cooperative dir encoding (27 entries) — overwrite s_emb slot ----
    __syncwarp(gm);   // all group lanes done reading layer-1 emb
    coop_encode<4>(s_emb[slot], dv.x, dv.y, dv.z, sub, gm);

    // ======== layer 4: 59 -> 32, relu =======================================
    {
        const float4* b4 = (const float4*)(l4b + c * 32) + sub;
        float4 b0 = __ldg(b4);
        acc[0] = b0.x; acc[1] = b0.y; acc[2] = b0.z; acc[3] = b0.w;
        const float4* w4 = (const float4*)(l4w + (size_t)c * 1888) + sub;
        #pragma unroll 4
        for (int g = 0; g < 8; g++) {
            int src = lanebase + g;
            #pragma unroll
            for (int j = 0; j < 4; j++) {
                float hv = __shfl_sync(gm, prev[j], src);
                fma4(hv, w4 + (g * 4 + j) * 8, acc);
            }
        }
        // dir part: rows 32..58 streamed from smem
        #pragma unroll
        for (int i4 = 0; i4 < 6; i4++) {
            float4 e = *(const float4*)(em + 4 * i4);
            fma4(e.x, w4 + (32 + 4 * i4 + 0) * 8, acc);
            fma4(e.y, w4 + (32 + 4 * i4 + 1) * 8, acc);
            fma4(e.z, w4 + (32 + 4 * i4 + 2) * 8, acc);
            fma4(e.w, w4 + (32 + 4 * i4 + 3) * 8, acc);
        }
        fma4(em[24], w4 + 56 * 8, acc);
        fma4(em[25], w4 + 57 * 8, acc);
        fma4(em[26], w4 + 58 * 8, acc);
        #pragma unroll
        for (int q = 0; q < 4; q++) prev[q] = fmaxf(acc[q], 0.0f);
    }

    // ======== layer 5: 32 -> 3, sigmoid =====================================
    {
        int o = min(sub, 2);
        const float* w5 = l5w + c * 96 + o;
        float a5 = __ldg(l5b + c * 3 + o);
        #pragma unroll 4
        for (int g = 0; g < 8; g++) {
            int src = lanebase + g;
            #pragma unroll
            for (int j = 0; j < 4; j++) {
                float hv = __shfl_sync(gm, prev[j], src);
                a5 = fmaf(hv, __ldg(w5 + (g * 4 + j) * 3), a5);
            }
        }
        float cv = 1.0f / (1.0f + expf(-a5));
        if (sub < 3)       out[3 * p + sub] = mask ? cv : 0.0f;
        else if (sub == 7) out[3 * P + p]   = mask ? dens : 0.0f;
    }
}

// ---------------- launch ----------------------------------------------------
extern "C" void kernel_launch(void* const* d_in, const int* in_sizes, int n_in,
                              void* d_out, int out_size) {
    const float* x   = (const float*)d_in[0];
    const float* d   = (const float*)d_in[1];
    const float* l1w = (const float*)d_in[2];
    const float* l1b = (const float*)d_in[3];
    const float* l2w = (const float*)d_in[4];
    const float* l2b = (const float*)d_in[5];
    const float* l3w = (const float*)d_in[6];
    const float* l3b = (const float*)d_in[7];
    const float* l4w = (const float*)d_in[8];
    const float* l4b = (const float*)d_in[9];
    const float* l5w = (const float*)d_in[10];
    const float* l5b = (const float*)d_in[11];
    float* out = (float*)d_out;

    int P = in_sizes[0] / 3;
    if (P > P_MAX) P = P_MAX;

    k_sort<<<SORT_BLOCKS, SORT_THREADS>>>(x, d, P);
    int threads = 8 * P;
    k_mlp<<<(threads + 255) / 256, 256>>>(l1w, l1b, l2w, l2b, l3w, l3b,
                                          l4w, l4b, l5w, l5b, out, P);
}

// round 9
// speedup vs baseline: 1.8122x; 1.0982x over previous
#include <cuda_runtime.h>
#include <math.h>

#define P_MAX  32768
#define NCELLS 4096
#define SORT_BLOCKS  148
#define SORT_THREADS 1024

// ---------------- device scratch (no allocation allowed) --------------------
__device__ int    g_counts[NCELLS];
__device__ int    g_cursor[NCELLS];
__device__ int    g_cell[P_MAX];
__device__ float4 g_pt[P_MAX];    // sorted (x0,x1,x2, bitcast(orig p))
__device__ float4 g_dir[P_MAX];   // sorted (d0,d1,d2, 0)
__device__ unsigned          g_bar_cnt;
__device__ volatile unsigned g_bar_gen;

// ---------------- helpers ---------------------------------------------------
__device__ __forceinline__ int cell_of(float x0, float x1, float x2) {
    float v0 = x0 / 0.1875f + 8.0f;
    float v1 = x1 / 0.1875f + 8.0f;
    float v2 = x2 / 0.1875f + 8.0f;
    int i0 = (int)v0; i0 = min(max(i0, 0), 15);
    int i1 = (int)v1; i1 = min(max(i1, 0), 15);
    int i2 = (int)v2; i2 = min(max(i2, 0), 15);
    return (i0 * 16 + i1) * 16 + i2;
}

__device__ __forceinline__ void gridbar() {
    __syncthreads();
    if (threadIdx.x == 0) {
        unsigned gen = g_bar_gen;
        __threadfence();
        unsigned arrived = atomicAdd(&g_bar_cnt, 1u);
        if (arrived == gridDim.x - 1) {
            g_bar_cnt = 0;
            __threadfence();
            g_bar_gen = gen + 1;
        } else {
            while (g_bar_gen == gen) { __nanosleep(64); }
            __threadfence();
        }
    }
    __syncthreads();
}

// ------- kernel 1: counting sort (persistent, 1024 threads/block) -----------
__global__ __launch_bounds__(SORT_THREADS) void k_sort(
    const float* __restrict__ x, const float* __restrict__ d, int P)
{
    int tid  = blockIdx.x * blockDim.x + threadIdx.x;
    int nthr = gridDim.x * blockDim.x;

    for (int c = tid; c < NCELLS; c += nthr) g_counts[c] = 0;
    gridbar();

    for (int p = tid; p < P; p += nthr) {
        int c = cell_of(x[3 * p], x[3 * p + 1], x[3 * p + 2]);
        g_cell[p] = c;
        atomicAdd(&g_counts[c], 1);
    }
    gridbar();

    if (blockIdx.x == 0) {            // exclusive scan: 1024 thr x 4 cells
        __shared__ int s[SORT_THREADS];
        int t = threadIdx.x;
        int4 v = ((const int4*)g_counts)[t];
        int sum = v.x + v.y + v.z + v.w;
        s[t] = sum;
        __syncthreads();
        #pragma unroll
        for (int off = 1; off < SORT_THREADS; off <<= 1) {
            int u = (t >= off) ? s[t - off] : 0;
            __syncthreads();
            s[t] += u;
            __syncthreads();
        }
        int base = s[t] - sum;        // exclusive
        g_cursor[4 * t + 0] = base;
        g_cursor[4 * t + 1] = base + v.x;
        g_cursor[4 * t + 2] = base + v.x + v.y;
        g_cursor[4 * t + 3] = base + v.x + v.y + v.z;
    }
    gridbar();

    for (int p = tid; p < P; p += nthr) {
        int c = g_cell[p];
        int pos = atomicAdd(&g_cursor[c], 1);
        g_pt[pos]  = make_float4(x[3 * p], x[3 * p + 1], x[3 * p + 2], __int_as_float(p));
        g_dir[pos] = make_float4(d[3 * p], d[3 * p + 1], d[3 * p + 2], 0.0f);
    }
}

// ---------------- MLP micro-op: 4 outputs, one float4 load ------------------
__device__ __forceinline__ void fma4(float hv, const float4* __restrict__ w4,
                                     float* __restrict__ acc) {
    float4 a = __ldg(w4);
    acc[0] = fmaf(hv, a.x, acc[0]); acc[1] = fmaf(hv, a.y, acc[1]);
    acc[2] = fmaf(hv, a.z, acc[2]); acc[3] = fmaf(hv, a.w, acc[3]);
}

// ---------------- kernel 2: MLP (8 threads / point, 4 outputs each) ---------
// EXACT round-4 configuration: proven 52.9us, regs=64, occ~41%.
__global__ __launch_bounds__(256, 4) void k_mlp(
    const float* __restrict__ l1w, const float* __restrict__ l1b,
    const float* __restrict__ l2w, const float* __restrict__ l2b,
    const float* __restrict__ l3w, const float* __restrict__ l3b,
    const float* __restrict__ l4w, const float* __restrict__ l4b,
    const float* __restrict__ l5w, const float* __restrict__ l5b,
    float* __restrict__ out, int P)
{
    int t   = blockIdx.x * 256 + threadIdx.x;
    int pi  = t >> 3;
    int sub = t & 7;
    if (pi >= P) return;

    float4 xv = g_pt[pi];
    float4 dv = g_dir[pi];
    int p = __float_as_int(xv.w);
    int c = cell_of(xv.x, xv.y, xv.z);
    bool mask = (fabsf(xv.x) < 1.5f) && (fabsf(xv.y) < 1.5f) && (fabsf(xv.z) < 1.5f);
    int lanebase = (threadIdx.x & 31) & ~7;   // lane of sub==0 for this point

    float acc[4], prev[4];

    // ======== layer 1: 63 -> 32, relu (inputs by recurrence) ================
    {
        const float4* b4 = (const float4*)(l1b + c * 32) + sub;
        float4 b0 = __ldg(b4);
        acc[0] = b0.x; acc[1] = b0.y; acc[2] = b0.z; acc[3] = b0.w;

        const float4* w1 = (const float4*)(l1w + (size_t)c * 2016) + sub;
        fma4(xv.x, w1 + 0 * 8, acc);
        fma4(xv.y, w1 + 1 * 8, acc);
        fma4(xv.z, w1 + 2 * 8, acc);
        float s0 = sinf(xv.x), c0 = cosf(xv.x);
        float s1 = sinf(xv.y), c1 = cosf(xv.y);
        float s2 = sinf(xv.z), c2 = cosf(xv.z);
        #pragma unroll 1
        for (int j = 0; j < 10; j++) {
            const float4* wr = w1 + (3 + 6 * j) * 8;
            fma4(s0, wr + 0 * 8, acc);
            fma4(s1, wr + 1 * 8, acc);
            fma4(s2, wr + 2 * 8, acc);
            fma4(c0, wr + 3 * 8, acc);
            fma4(c1, wr + 4 * 8, acc);
            fma4(c2, wr + 5 * 8, acc);
            float n0 = 2.0f * s0 * c0, m0 = 1.0f - 2.0f * s0 * s0;
            float n1 = 2.0f * s1 * c1, m1 = 1.0f - 2.0f * s1 * s1;
            float n2 = 2.0f * s2 * c2, m2 = 1.0f - 2.0f * s2 * s2;
            s0 = n0; c0 = m0; s1 = n1; c1 = m1; s2 = n2; c2 = m2;
        }
        #pragma unroll
        for (int q = 0; q < 4; q++) prev[q] = fmaxf(acc[q], 0.0f);
    }

    // ======== layer 2: 32 -> 33 (stride 33, scalar), relu; col32 = density ==
    float dens = 0.0f;
    {
        int o0 = sub * 4;
        const float* base = l2w + (size_t)c * 1056 + o0;
        #pragma unroll
        for (int q = 0; q < 4; q++) acc[q] = __ldg(l2b + c * 33 + o0 + q);
        if (sub == 7) dens = __ldg(l2b + c * 33 + 32);
        #pragma unroll 2
        for (int g = 0; g < 8; g++) {
            int src = lanebase + g;
            #pragma unroll
            for (int j = 0; j < 4; j++) {
                float hv = __shfl_sync(0xffffffffu, prev[j], src);
                const float* wr = base + (g * 4 + j) * 33;
                acc[0] = fmaf(hv, __ldg(wr + 0), acc[0]);
                acc[1] = fmaf(hv, __ldg(wr + 1), acc[1]);
                acc[2] = fmaf(hv, __ldg(wr + 2), acc[2]);
                acc[3] = fmaf(hv, __ldg(wr + 3), acc[3]);
                if (sub == 7) dens = fmaf(hv, __ldg(wr + 4), dens);  // o0=28 -> col 32
            }
        }
        dens = fmaxf(dens, 0.0f);
        #pragma unroll
        for (int q = 0; q < 4; q++) { float v = acc[q]; prev[q] = fmaxf(v, 0.0f); }
    }

    // ======== layer 3: 32 -> 32, NO activation ==============================
    {
        const float4* b4 = (const float4*)(l3b + c * 32) + sub;
        float4 b0 = __ldg(b4);
        acc[0] = b0.x; acc[1] = b0.y; acc[2] = b0.z; acc[3] = b0.w;
        const float4* w3 = (const float4*)(l3w + (size_t)c * 1024) + sub;
        #pragma unroll 2
        for (int g = 0; g < 8; g++) {
            int src = lanebase + g;
            #pragma unroll
            for (int j = 0; j < 4; j++) {
                float hv = __shfl_sync(0xffffffffu, prev[j], src);
                fma4(hv, w3 + (g * 4 + j) * 8, acc);
            }
        }
        #pragma unroll
        for (int q = 0; q < 4; q++) prev[q] = acc[q];
    }

    // ======== layer 4: 59 -> 32, relu (32 via shfl + 27 dir recurrence) =====
    {
        const float4* b4 = (const float4*)(l4b + c * 32) + sub;
        float4 b0 = __ldg(b4);
        acc[0] = b0.x; acc[1] = b0.y; acc[2] = b0.z; acc[3] = b0.w;
        const float4* w4 = (const float4*)(l4w + (size_t)c * 1888) + sub;
        #pragma unroll 2
        for (int g = 0; g < 8; g++) {
            int src = lanebase + g;
            #pragma unroll
            for (int j = 0; j < 4; j++) {
                float hv = __shfl_sync(0xffffffffu, prev[j], src);
                fma4(hv, w4 + (g * 4 + j) * 8, acc);
            }
        }
        fma4(dv.x, w4 + 32 * 8, acc);
        fma4(dv.y, w4 + 33 * 8, acc);
        fma4(dv.z, w4 + 34 * 8, acc);
        float s0 = sinf(dv.x), c0 = cosf(dv.x);
        float s1 = sinf(dv.y), c1 = cosf(dv.y);
        float s2 = sinf(dv.z), c2 = cosf(dv.z);
        #pragma unroll 1
        for (int j = 0; j < 4; j++) {
            const float4* wr = w4 + (35 + 6 * j) * 8;
            fma4(s0, wr + 0 * 8, acc);
            fma4(s1, wr + 1 * 8, acc);
            fma4(s2, wr + 2 * 8, acc);
            fma4(c0, wr + 3 * 8, acc);
            fma4(c1, wr + 4 * 8, acc);
            fma4(c2, wr + 5 * 8, acc);
            float n0 = 2.0f * s0 * c0, m0 = 1.0f - 2.0f * s0 * s0;
            float n1 = 2.0f * s1 * c1, m1 = 1.0f - 2.0f * s1 * s1;
            float n2 = 2.0f * s2 * c2, m2 = 1.0f - 2.0f * s2 * s2;
            s0 = n0; c0 = m0; s1 = n1; c1 = m1; s2 = n2; c2 = m2;
        }
        #pragma unroll
        for (int q = 0; q < 4; q++) prev[q] = fmaxf(acc[q], 0.0f);
    }

    // ======== layer 5: 32 -> 3, sigmoid =====================================
    {
        int o = min(sub, 2);
        const float* w5 = l5w + c * 96 + o;
        float a5 = __ldg(l5b + c * 3 + o);
        #pragma unroll 2
        for (int g = 0; g < 8; g++) {
            int src = lanebase + g;
            #pragma unroll
            for (int j = 0; j < 4; j++) {
                float hv = __shfl_sync(0xffffffffu, prev[j], src);
                a5 = fmaf(hv, __ldg(w5 + (g * 4 + j) * 3), a5);
            }
        }
        float cv = 1.0f / (1.0f + expf(-a5));
        if (sub < 3)       out[3 * p + sub] = mask ? cv : 0.0f;
        else if (sub == 7) out[3 * P + p]   = mask ? dens : 0.0f;
    }
}

// ---------------- launch ----------------------------------------------------
extern "C" void kernel_launch(void* const* d_in, const int* in_sizes, int n_in,
                              void* d_out, int out_size) {
    const float* x   = (const float*)d_in[0];
    const float* d   = (const float*)d_in[1];
    const float* l1w = (const float*)d_in[2];
    const float* l1b = (const float*)d_in[3];
    const float* l2w = (const float*)d_in[4];
    const float* l2b = (const float*)d_in[5];
    const float* l3w = (const float*)d_in[6];
    const float* l3b = (const float*)d_in[7];
    const float* l4w = (const float*)d_in[8];
    const float* l4b = (const float*)d_in[9];
    const float* l5w = (const float*)d_in[10];
    const float* l5b = (const float*)d_in[11];
    float* out = (float*)d_out;

    int P = in_sizes[0] / 3;
    if (P > P_MAX) P = P_MAX;

    k_sort<<<SORT_BLOCKS, SORT_THREADS>>>(x, d, P);
    int threads = 8 * P;
    k_mlp<<<(threads + 255) / 256, 256>>>(l1w, l1b, l2w, l2b, l3w, l3b,
                                          l4w, l4b, l5w, l5b, out, P);
}